// round 16
// baseline (speedup 1.0000x reference)
#include <cuda_runtime.h>
#include <math.h>
#include <stdint.h>

// ln(2)^2 — final scale converting lg2-unit squared-loss into natural-log units
#define LN2SQ 0.4804530139182014

// statically-zeroed accumulators; kernel self-resets them after each use,
// so the zero-invariant holds across the correctness run and every graph replay.
__device__ double g_accum = 0.0;
__device__ unsigned int g_count = 0u;

// ---- flag-independent fast approx intrinsics (MUFU paths) ----
__device__ __forceinline__ float f_rcp(float x)   { float y; asm("rcp.approx.f32 %0, %1;"   : "=f"(y) : "f"(x)); return y; }
__device__ __forceinline__ float f_rsqrt(float x) { float y; asm("rsqrt.approx.f32 %0, %1;" : "=f"(y) : "f"(x)); return y; }
__device__ __forceinline__ float f_sqrt(float x)  { float y; asm("sqrt.approx.f32 %0, %1;"  : "=f"(y) : "f"(x)); return y; }
__device__ __forceinline__ float f_lg2(float x)   { float y; asm("lg2.approx.f32 %0, %1;"   : "=f"(y) : "f"(x)); return y; }
__device__ __forceinline__ float f_cos(float x)   { float y; asm("cos.approx.f32 %0, %1;"   : "=f"(y) : "f"(x)); return y; }

// acos(r)/3 via A&S 4.4.45 degree-3 (|err| <= 5e-5/3 rad — eigenvalue error
// ~1e-5 relative, far inside the 1e-3 budget; the degree-7 version was
// overspecified). Coefficients pre-divided by 3; reflection constant pi/3.
// 4 fewer FMAs on the serial critical path per matrix.
__device__ __forceinline__ float fast_acos_third(float r) {
    float a = fabsf(r);                      // <= 1 exactly (r was clamped)
    float p = -0.0062431f;                   // -0.0187293 / 3
    p = fmaf(p, a,  0.02475367f);            //  0.0742610 / 3
    p = fmaf(p, a, -0.0707048f);             // -0.2121144 / 3
    p = fmaf(p, a,  0.52357627f);            //  1.5707288 / 3
    float t = f_sqrt(1.0f - a) * p;          // 1-a >= 0 exactly
    return (r < 0.0f) ? (1.0471975512f - t) : t;   // pi/3 - t
}

struct Sym3 { float m00, m10, m11, m20, m21, m22; };

// logm (in lg2 units) of a 3x3 SPD matrix — the proven R9/R11/R15 path:
// trig eigenvalues, short acos/3 poly, single-rcp clamped Newton divided diffs.
__device__ __forceinline__ void log_spd3(const float* __restrict__ g, Sym3& L) {
    float a00 = g[0];
    float a10 = g[3];
    float a11 = g[4];
    float a20 = g[6];
    float a21 = g[7];
    float a22 = g[8];

    // ---- eigenvalues: trigonometric method (Smith) ----
    float q   = (a00 + a11 + a22) * (1.0f / 3.0f);
    float b00 = a00 - q, b11 = a11 - q, b22 = a22 - q;
    float p1  = a10 * a10 + a20 * a20 + a21 * a21;
    float p2  = b00 * b00 + b11 * b11 + b22 * b22 + 2.0f * p1;
    float x   = p2 * (1.0f / 6.0f);
    float rs  = f_rsqrt(fmaxf(x, 1e-30f));   // 1/sqrt(x); clamp guards NaN path
    float p   = x * rs;                      // sqrt(x)

    float detB = b00 * (b11 * b22 - a21 * a21)
               - a10 * (a10 * b22 - a21 * a20)
               + a20 * (a10 * a21 - b11 * a20);
    float r = detB * (rs * rs) * (0.5f * rs);
    r = fmaxf(-1.0f, fminf(1.0f, r));        // also squashes NaN -> 1

    float phi = fast_acos_third(r);          // acos(r)/3
    float tp  = 2.0f * p;
    float w0 = fmaf(tp, f_cos(phi), q);                          // largest
    float w2 = fmaf(tp, f_cos(phi + 2.0943951023931953f), q);    // smallest
    float w1 = fmaf(3.0f, q, -w0) - w2;                          // middle

    // logs in base-2; final loss rescaled once by ln(2)^2
    float f0 = f_lg2(w0);
    float f1 = f_lg2(w1);
    float f2 = f_lg2(w2);

    // ---- branch-free Newton divided differences, ONE rcp ----
    float dlt = 2e-4f * q;
    float e01 = fmaxf(w0 - w1, dlt);
    float e12 = fmaxf(w1 - w2, dlt);
    float e02 = e01 + e12;
    float rall = f_rcp(e01 * (e12 * e02));
    float df01 = f0 - f1;
    float df12 = f1 - f2;
    float d01 = df01 * (e12 * e02) * rall;
    float gam = fmaf(df01, e12, -df12 * e01) * rall;
    float bet = d01 - gam * (w0 + w1);
    float alp = f0 - d01 * w0 + gam * (w0 * w1);

    // ---- A^2 (symmetric, 6 unique entries) ----
    float s00 = a00 * a00 + a10 * a10 + a20 * a20;
    float s11 = a10 * a10 + a11 * a11 + a21 * a21;
    float s22 = a20 * a20 + a21 * a21 + a22 * a22;
    float s10 = a10 * (a00 + a11) + a20 * a21;
    float s20 = a20 * (a00 + a22) + a10 * a21;
    float s21 = a21 * (a11 + a22) + a10 * a20;

    L.m00 = alp + bet * a00 + gam * s00;
    L.m11 = alp + bet * a11 + gam * s11;
    L.m22 = alp + bet * a22 + gam * s22;
    L.m10 = bet * a10 + gam * s10;
    L.m20 = bet * a20 + gam * s20;
    L.m21 = bet * a21 + gam * s21;
}

__global__ void __launch_bounds__(256)
loss_kernel(const float* __restrict__ d1, const float* __restrict__ d2,
            int nmat, float* __restrict__ out, double inv_n, unsigned int nblocks) {
    int i = blockIdx.x * blockDim.x + threadIdx.x;
    float s = 0.0f;
    if (i < nmat) {
        size_t off = (size_t)i * 9;
        Sym3 L1, L2;
        log_spd3(d1 + off, L1);
        log_spd3(d2 + off, L2);
        float t, soff = 0.0f;
        t = L1.m00 - L2.m00; s    = fmaf(t, t, s);
        t = L1.m11 - L2.m11; s    = fmaf(t, t, s);
        t = L1.m22 - L2.m22; s    = fmaf(t, t, s);
        t = L1.m10 - L2.m10; soff = fmaf(t, t, soff);
        t = L1.m20 - L2.m20; soff = fmaf(t, t, soff);
        t = L1.m21 - L2.m21; soff = fmaf(t, t, soff);
        s = fmaf(2.0f, soff, s);   // symmetric off-diagonals count twice
    }

    // ---- block reduction ----
    #pragma unroll
    for (int off = 16; off > 0; off >>= 1)
        s += __shfl_xor_sync(0xffffffffu, s, off);

    __shared__ float sh[8];
    int lane = threadIdx.x & 31;
    int warp = threadIdx.x >> 5;
    if (lane == 0) sh[warp] = s;
    __syncthreads();
    if (warp == 0) {
        float v = (lane < 8) ? sh[lane] : 0.0f;
        #pragma unroll
        for (int off = 4; off > 0; off >>= 1)
            v += __shfl_xor_sync(0xffu, v, off);
        if (lane == 0) {
            atomicAdd(&g_accum, (double)v);
            __threadfence();
            // ticket wraps to 0 at nblocks-1: self-resets for the next replay
            unsigned int ticket = atomicInc(&g_count, nblocks - 1u);
            if (ticket == nblocks - 1u) {
                out[0] = (float)(g_accum * inv_n);
                g_accum = 0.0;    // restore invariant for next call/replay
            }
        }
    }
}

extern "C" void kernel_launch(void* const* d_in, const int* in_sizes, int n_in,
                              void* d_out, int out_size) {
    const float* d1 = (const float*)d_in[0];
    const float* d2 = (const float*)d_in[1];
    int n_elems = in_sizes[0];          // nmat * 9
    int nmat = n_elems / 9;

    int threads = 256;
    unsigned int blocks = (unsigned int)((nmat + threads - 1) / threads);
    // inv_n includes the ln(2)^2 rescale (logs computed in base 2)
    double inv_n = LN2SQ / (double)n_elems;
    loss_kernel<<<blocks, threads>>>(d1, d2, nmat, (float*)d_out, inv_n, blocks);
}

// round 17
// speedup vs baseline: 1.0020x; 1.0020x over previous
#include <cuda_runtime.h>
#include <math.h>
#include <stdint.h>

// ln(2)^2 — final scale converting lg2-unit squared-loss into natural-log units
#define LN2SQ 0.4804530139182014

// statically-zeroed accumulators; kernel self-resets them after each use,
// so the zero-invariant holds across the correctness run and every graph replay.
__device__ double g_accum = 0.0;
__device__ unsigned int g_count = 0u;

// ---- flag-independent fast approx intrinsics (MUFU paths) ----
__device__ __forceinline__ float f_rcp(float x)   { float y; asm("rcp.approx.f32 %0, %1;"   : "=f"(y) : "f"(x)); return y; }
__device__ __forceinline__ float f_rsqrt(float x) { float y; asm("rsqrt.approx.f32 %0, %1;" : "=f"(y) : "f"(x)); return y; }
__device__ __forceinline__ float f_sqrt(float x)  { float y; asm("sqrt.approx.f32 %0, %1;"  : "=f"(y) : "f"(x)); return y; }
__device__ __forceinline__ float f_lg2(float x)   { float y; asm("lg2.approx.f32 %0, %1;"   : "=f"(y) : "f"(x)); return y; }
__device__ __forceinline__ float f_cos(float x)   { float y; asm("cos.approx.f32 %0, %1;"   : "=f"(y) : "f"(x)); return y; }

// acos(r)/3 via A&S 4.4.45 degree-3 (|err| <= 5e-5/3 rad), coefficients
// pre-divided by 3; reflection constant pi/3.
__device__ __forceinline__ float fast_acos_third(float r) {
    float a = fabsf(r);                      // <= 1 exactly (r was clamped)
    float p = -0.0062431f;                   // -0.0187293 / 3
    p = fmaf(p, a,  0.02475367f);            //  0.0742610 / 3
    p = fmaf(p, a, -0.0707048f);             // -0.2121144 / 3
    p = fmaf(p, a,  0.52357627f);            //  1.5707288 / 3
    float t = f_sqrt(1.0f - a) * p;          // 1-a >= 0 exactly
    return (r < 0.0f) ? (1.0471975512f - t) : t;   // pi/3 - t
}

struct Sym3 { float m00, m10, m11, m20, m21, m22; };

// logm (in lg2 units) of a 3x3 SPD matrix — the proven R9/R11/R15/R16 path,
// with p2 computed via tr(A^2) - 3q^2 reusing the A^2 diagonal that the
// L-assembly needs anyway (saves p1 + the three b^2 FMAs; p2 ready earlier).
__device__ __forceinline__ void log_spd3(const float* __restrict__ g, Sym3& L) {
    float a00 = g[0];
    float a10 = g[3];
    float a11 = g[4];
    float a20 = g[6];
    float a21 = g[7];
    float a22 = g[8];

    // ---- A^2 entries first (diagonal reused for p2) ----
    float sq10 = a10 * a10, sq20 = a20 * a20, sq21 = a21 * a21;
    float s00 = fmaf(a00, a00, sq10 + sq20);
    float s11 = fmaf(a11, a11, sq10 + sq21);
    float s22 = fmaf(a22, a22, sq20 + sq21);
    float s10 = a10 * (a00 + a11) + a20 * a21;
    float s20 = a20 * (a00 + a22) + a10 * a21;
    float s21 = a21 * (a11 + a22) + a10 * a20;

    // ---- eigenvalues: trigonometric method (Smith) ----
    float q  = (a00 + a11 + a22) * (1.0f / 3.0f);
    // p2 = sum (w_i - q)^2 = tr(A^2) - 3 q^2
    float p2 = (s00 + s11 + s22) - 3.0f * q * q;
    float x  = p2 * (1.0f / 6.0f);
    float rs = f_rsqrt(fmaxf(x, 1e-30f));    // 1/sqrt(x); clamp guards NaN path
    float p  = x * rs;                       // sqrt(x)

    float b00 = a00 - q, b11 = a11 - q, b22 = a22 - q;
    float detB = b00 * (b11 * b22 - sq21)
               - a10 * (a10 * b22 - a21 * a20)
               + a20 * (a10 * a21 - b11 * a20);
    float r = detB * (rs * rs) * (0.5f * rs);
    r = fmaxf(-1.0f, fminf(1.0f, r));        // also squashes NaN -> 1

    float phi = fast_acos_third(r);          // acos(r)/3
    float tp  = 2.0f * p;
    float w0 = fmaf(tp, f_cos(phi), q);                          // largest
    float w2 = fmaf(tp, f_cos(phi + 2.0943951023931953f), q);    // smallest
    float w1 = fmaf(3.0f, q, -w0) - w2;                          // middle

    // logs in base-2; final loss rescaled once by ln(2)^2
    float f0 = f_lg2(w0);
    float f1 = f_lg2(w1);
    float f2 = f_lg2(w2);

    // ---- branch-free Newton divided differences, ONE rcp ----
    float dlt = 2e-4f * q;
    float e01 = fmaxf(w0 - w1, dlt);
    float e12 = fmaxf(w1 - w2, dlt);
    float e02 = e01 + e12;
    float rall = f_rcp(e01 * (e12 * e02));
    float df01 = f0 - f1;
    float df12 = f1 - f2;
    float d01 = df01 * (e12 * e02) * rall;
    float gam = fmaf(df01, e12, -df12 * e01) * rall;
    float bet = d01 - gam * (w0 + w1);
    float alp = f0 - d01 * w0 + gam * (w0 * w1);

    L.m00 = alp + bet * a00 + gam * s00;
    L.m11 = alp + bet * a11 + gam * s11;
    L.m22 = alp + bet * a22 + gam * s22;
    L.m10 = bet * a10 + gam * s10;
    L.m20 = bet * a20 + gam * s20;
    L.m21 = bet * a21 + gam * s21;
}

// Persistent grid-stride kernel: ~1184 CTAs (one resident wave), each thread
// walks ~7 pairs. Amortizes the reduction/epilogue over the loop and removes
// the 7-wave launch-quantization tail. Body/registers unchanged vs R16 —
// NOT an ILP reshape (unroll 1 keeps one pair in flight).
__global__ void __launch_bounds__(256)
loss_kernel(const float* __restrict__ d1, const float* __restrict__ d2,
            int nmat, float* __restrict__ out, double inv_n, unsigned int nblocks) {
    int stride = gridDim.x * blockDim.x;
    float s = 0.0f, soff = 0.0f;
    #pragma unroll 1
    for (int i = blockIdx.x * blockDim.x + threadIdx.x; i < nmat; i += stride) {
        size_t off = (size_t)i * 9;
        Sym3 L1, L2;
        log_spd3(d1 + off, L1);
        log_spd3(d2 + off, L2);
        float t;
        t = L1.m00 - L2.m00; s    = fmaf(t, t, s);
        t = L1.m11 - L2.m11; s    = fmaf(t, t, s);
        t = L1.m22 - L2.m22; s    = fmaf(t, t, s);
        t = L1.m10 - L2.m10; soff = fmaf(t, t, soff);
        t = L1.m20 - L2.m20; soff = fmaf(t, t, soff);
        t = L1.m21 - L2.m21; soff = fmaf(t, t, soff);
    }
    s = fmaf(2.0f, soff, s);   // symmetric off-diagonals count twice

    // ---- block reduction ----
    #pragma unroll
    for (int off = 16; off > 0; off >>= 1)
        s += __shfl_xor_sync(0xffffffffu, s, off);

    __shared__ float sh[8];
    int lane = threadIdx.x & 31;
    int warp = threadIdx.x >> 5;
    if (lane == 0) sh[warp] = s;
    __syncthreads();
    if (warp == 0) {
        float v = (lane < 8) ? sh[lane] : 0.0f;
        #pragma unroll
        for (int off = 4; off > 0; off >>= 1)
            v += __shfl_xor_sync(0xffu, v, off);
        if (lane == 0) {
            atomicAdd(&g_accum, (double)v);
            __threadfence();
            // ticket wraps to 0 at nblocks-1: self-resets for the next replay
            unsigned int ticket = atomicInc(&g_count, nblocks - 1u);
            if (ticket == nblocks - 1u) {
                out[0] = (float)(g_accum * inv_n);
                g_accum = 0.0;    // restore invariant for next call/replay
            }
        }
    }
}

extern "C" void kernel_launch(void* const* d_in, const int* in_sizes, int n_in,
                              void* d_out, int out_size) {
    const float* d1 = (const float*)d_in[0];
    const float* d2 = (const float*)d_in[1];
    int n_elems = in_sizes[0];          // nmat * 9
    int nmat = n_elems / 9;

    int threads = 256;
    // one resident wave: ~148 SMs x 8 CTAs (regs=32 -> 8 CTAs/SM at 256 thr)
    unsigned int max_blocks = 1184u;
    unsigned int need = (unsigned int)((nmat + threads - 1) / threads);
    unsigned int blocks = need < max_blocks ? need : max_blocks;
    // inv_n includes the ln(2)^2 rescale (logs computed in base 2)
    double inv_n = LN2SQ / (double)n_elems;
    loss_kernel<<<blocks, threads>>>(d1, d2, nmat, (float*)d_out, inv_n, blocks);
}